// round 1
// baseline (speedup 1.0000x reference)
#include <cuda_runtime.h>
#include <cuda_bf16.h>

#define NUM_BINS 20
#define THREADS 256
#define BLOCKS 740  // 148 SMs * 5 resident blocks (40KB smem/block)

// scratch: [0..19] = per-bin sum of squared error, [20..39] = per-bin counts
__device__ float g_bin[2 * NUM_BINS];

__global__ void dwmse_init_kernel() {
    int i = threadIdx.x;
    if (i < 2 * NUM_BINS) g_bin[i] = 0.0f;
}

__device__ __forceinline__ void accum_one(float p, float t, float2* acc, int tid) {
    float d = p - t;
    float se = d * d;
    int b = (int)floorf(t * (float)NUM_BINS);
    b = min(max(b, 0), NUM_BINS - 1);
    float2 v = acc[b * THREADS + tid];
    v.x += se;
    v.y += 1.0f;
    acc[b * THREADS + tid] = v;
}

__global__ void __launch_bounds__(THREADS)
dwmse_hist_kernel(const float* __restrict__ pred,
                  const float* __restrict__ target,
                  int n) {
    // per-thread privatized (sumsq, count) accumulators: [bin][tid] layout
    // -> lane-consecutive addresses, bank-conflict-free, zero atomics in loop
    __shared__ float2 acc[NUM_BINS * THREADS];
    const int tid = threadIdx.x;

#pragma unroll
    for (int b = 0; b < NUM_BINS; b++)
        acc[b * THREADS + tid] = make_float2(0.0f, 0.0f);
    __syncthreads();

    const int n4 = n >> 2;
    const float4* __restrict__ p4 = (const float4*)pred;
    const float4* __restrict__ t4 = (const float4*)target;
    const int stride = gridDim.x * blockDim.x;

    for (int i = blockIdx.x * blockDim.x + tid; i < n4; i += stride) {
        float4 p = p4[i];
        float4 t = t4[i];
        accum_one(p.x, t.x, acc, tid);
        accum_one(p.y, t.y, acc, tid);
        accum_one(p.z, t.z, acc, tid);
        accum_one(p.w, t.w, acc, tid);
    }

    // scalar tail (N=2^24 is divisible by 4, but stay safe)
    if (blockIdx.x == 0) {
        for (int i = (n4 << 2) + tid; i < n; i += THREADS)
            accum_one(pred[i], target[i], acc, tid);
    }
    __syncthreads();

    // tree-reduce the 256 per-thread copies of each bin
    for (int s = THREADS / 2; s > 0; s >>= 1) {
        if (tid < s) {
#pragma unroll
            for (int b = 0; b < NUM_BINS; b++) {
                float2 a = acc[b * THREADS + tid];
                float2 c = acc[b * THREADS + tid + s];
                a.x += c.x;
                a.y += c.y;
                acc[b * THREADS + tid] = a;
            }
        }
        __syncthreads();
    }

    if (tid < NUM_BINS) {
        float2 v = acc[tid * THREADS];
        atomicAdd(&g_bin[tid], v.x);             // sum of squared errors
        atomicAdd(&g_bin[NUM_BINS + tid], v.y);  // counts
    }
}

__global__ void dwmse_finalize_kernel(float* __restrict__ out, float inv_n) {
    if (threadIdx.x == 0 && blockIdx.x == 0) {
        double w[NUM_BINS];
        double s = 0.0;
#pragma unroll
        for (int b = 0; b < NUM_BINS; b++) {
            double c = (double)g_bin[NUM_BINS + b];
            if (c < 1.0) c = 1.0;
            w[b] = pow(c, -0.9);
            s += w[b];
        }
        double total = 0.0;
#pragma unroll
        for (int b = 0; b < NUM_BINS; b++) {
            double wb = w[b];
            if (s > 0.0) wb = wb / s * (double)NUM_BINS;
            if (wb < 1.0) wb = 1.0;
            total += wb * (double)g_bin[b];
        }
        out[0] = (float)(total * (double)inv_n);
    }
}

extern "C" void kernel_launch(void* const* d_in, const int* in_sizes, int n_in,
                              void* d_out, int out_size) {
    const float* pred = (const float*)d_in[0];
    const float* target = (const float*)d_in[1];
    float* out = (float*)d_out;
    const int n = in_sizes[0];

    dwmse_init_kernel<<<1, 64>>>();
    dwmse_hist_kernel<<<BLOCKS, THREADS>>>(pred, target, n);
    dwmse_finalize_kernel<<<1, 32>>>(out, 1.0f / (float)n);
}